// round 8
// baseline (speedup 1.0000x reference)
#include <cuda_runtime.h>

#define NH 192            // nH = nW = 193 - 2 + 1
#define HG 193            // grid H/W
#define MD 64             // vec dim m
#define PITCH 68          // padded row (floats): conflict-free float4 LDS (68 % 32 == 4)

// Scratch (allocation-free rule: __device__ globals)
__device__ float g_cosT[NH * MD * MD];   // cos(2*pi*k / T[i,j]),  3 MB
__device__ float g_x[NH * NH * MD];      // x = win_avg(grid) @ M^T, 9.4 MB

// ---- packed f32x2 helpers (FFMA2/FMUL2 only reachable via PTX) -------------
__device__ __forceinline__ unsigned long long pk(float x, float y) {
    unsigned long long r;
    asm("mov.b64 %0, {%1, %2};" : "=l"(r) : "f"(x), "f"(y));
    return r;
}
__device__ __forceinline__ float2 upk(unsigned long long v) {
    float2 t;
    asm("mov.b64 {%0, %1}, %2;" : "=f"(t.x), "=f"(t.y) : "l"(v));
    return t;
}
__device__ __forceinline__ unsigned long long mul2(unsigned long long a,
                                                   unsigned long long b) {
    unsigned long long r;
    asm("mul.rn.f32x2 %0, %1, %2;" : "=l"(r) : "l"(a), "l"(b));
    return r;
}
__device__ __forceinline__ unsigned long long fma2(unsigned long long a,
                                                   unsigned long long b,
                                                   unsigned long long c) {
    unsigned long long r;
    asm("fma.rn.f32x2 %0, %1, %2, %3;" : "=l"(r) : "l"(a), "l"(b), "l"(c));
    return r;
}

// ---------------------------------------------------------------------------
// Fused prep kernel.
//   CTAs [0, 3072):     cos table  cosT[k,i,j] = cosf(2*pi*k/(i*64+j+2))
//   CTAs [3072, 4224):  x = win_avg(grid) @ M^T  — 3 barriers total:
//       stage M (pitch 66) -> Mreg(f32x2) | stage all 32 wavg rows | 8 f32x2 dots
// ---------------------------------------------------------------------------
__global__ void __launch_bounds__(256) fused_prep(const float* __restrict__ grid,
                                                  const float* __restrict__ Mw) {
    __shared__ __align__(16) float sbuf[66 * 64];   // M staging (pitch 66) / wavg (pitch 64)

    int t = threadIdx.x;

    if (blockIdx.x < 3072) {
        int idx = blockIdx.x * 256 + t;
        int k = idx >> 12;
        int r = idx & 4095;
        int i = r >> 6;
        int j = r & 63;
        float period = (float)(i * MD + j + 2);
        float arg = 6.2831853071795864769f * (float)k / period;  // fp32, matches ref
        g_cosT[idx] = cosf(arg);
        return;
    }

    int bid = blockIdx.x - 3072;      // 0..1151
    int q  = t >> 6;                  // 0..3  (warp-uniform)
    int jl = t & 63;

    int k1     = bid / 6;
    int k2base = (bid % 6) * 32;

    // --- stage M with pitch 66 (row reads conflict-free), pack row jl ---
    for (int e = t; e < 4096; e += 256) sbuf[(e >> 6) * 66 + (e & 63)] = Mw[e];
    __syncthreads();
    unsigned long long Mp[32];
#pragma unroll
    for (int l = 0; l < 32; l++)
        Mp[l] = pk(sbuf[jl * 66 + 2 * l], sbuf[jl * 66 + 2 * l + 1]);
    __syncthreads();                  // done reading M from sbuf

    // --- stage all 32 wavg rows (pitch 64; reads are broadcast-only) ---
#pragma unroll
    for (int r = 0; r < 8; r++) {
        int e   = t + 256 * r;
        int row = e >> 6;             // k2 offset 0..31
        int col = e & 63;
        const float* g00 = grid + ((k1 * HG + k2base + row) * MD) + col;
        sbuf[row * 64 + col] = 0.25f * (g00[0] + g00[MD] +
                                        g00[HG * MD] + g00[HG * MD + MD]);
    }
    __syncthreads();

    // --- 8 dots per thread: x[k1, k2base + q + 4r, jl] ---
#pragma unroll
    for (int r = 0; r < 8; r++) {
        int k2r = q + 4 * r;
        const ulonglong2* w2 = reinterpret_cast<const ulonglong2*>(&sbuf[k2r * 64]);
        unsigned long long a0 = 0ULL, a1 = 0ULL;
#pragma unroll
        for (int l = 0; l < 16; l++) {
            ulonglong2 w = w2[l];     // warp-uniform row -> broadcast
            a0 = fma2(Mp[2 * l],     w.x, a0);
            a1 = fma2(Mp[2 * l + 1], w.y, a1);
        }
        float2 f0 = upk(a0), f1 = upk(a1);
        g_x[(k1 * NH + k2base + k2r) * MD + jl] = (f0.x + f0.y) + (f1.x + f1.y);
    }
}

// ---------------------------------------------------------------------------
// Main kernel: Nk[b,i] = sum_j x[b,j] * (P[i,j]*cosT[k1,i,j]) * cosT[k2,i,j]
//
// 512 threads = (k1sub 0..7) x (i 0..63), ONE output/thread/k2 (R6 skeleton).
// Grid (6 k2-chunks, 24 k1-tiles) = 144 CTAs = one wave.
// R8 deltas: direct-LDG C1 build (no staged build, no Ps smem);
//            DOUBLE-BUFFERED cos/x staging with ONE barrier per iteration.
// ---------------------------------------------------------------------------
__global__ void __launch_bounds__(512, 1) main_kernel(const float* __restrict__ P,
                                                      float* __restrict__ out) {
    __shared__ __align__(16) float cbuf[2][64 * PITCH];   // 2 x 17.4 KB
    __shared__ __align__(16) float xsm[2][8 * 64];

    int t      = threadIdx.x;
    int i      = t & 63;
    int k1sub  = t >> 6;                // 0..7
    int k1base = blockIdx.y * 8;
    int k1     = k1base + k1sub;

    // --- C1 build: direct LDG of own cos1 row and P row (one-time) ---
    unsigned long long C1p[32];
    {
        const float4* crow = reinterpret_cast<const float4*>(g_cosT + (k1 * MD + i) * MD);
        const float4* prow = reinterpret_cast<const float4*>(P + i * MD);
#pragma unroll
        for (int m = 0; m < 16; m++) {
            float4 c = crow[m];
            float4 p = prow[m];
            C1p[2 * m]     = pk(c.x * p.x, c.y * p.y);
            C1p[2 * m + 1] = pk(c.z * p.z, c.w * p.w);
        }
    }

    int k2base = blockIdx.x * 32;
    int xrow   = t >> 6;                // 0..7
    int xcol   = t & 63;

    // --- prologue: fill buf0 with slice k2base; preload slice k2base+1 ---
    float4 pre0, pre1;
    float  xpre;
    {
        const float4* src = reinterpret_cast<const float4*>(g_cosT + k2base * 4096);
        pre0 = src[t];
        pre1 = src[t + 512];
        xpre = g_x[((k1base + xrow) * NH + k2base) * MD + xcol];
        int e0 = t * 4, e1 = (t + 512) * 4;
        *reinterpret_cast<float4*>(&cbuf[0][(e0 >> 6) * PITCH + (e0 & 63)]) = pre0;
        *reinterpret_cast<float4*>(&cbuf[0][(e1 >> 6) * PITCH + (e1 & 63)]) = pre1;
        xsm[0][xrow * 64 + xcol] = xpre;

        const float4* s1 = reinterpret_cast<const float4*>(g_cosT + (k2base + 1) * 4096);
        pre0 = s1[t];
        pre1 = s1[t + 512];
        xpre = g_x[((k1base + xrow) * NH + (k2base + 1)) * MD + xcol];
    }
    __syncthreads();

    for (int kk = 0; kk < 32; kk++) {
        int cur = kk & 1;

        // STS slice kk+1 into the other buffer (its readers finished at the
        // barrier ending iter kk-1); then issue LDGs for slice kk+2.
        if (kk + 1 < 32) {
            int e0 = t * 4, e1 = (t + 512) * 4;
            *reinterpret_cast<float4*>(&cbuf[cur ^ 1][(e0 >> 6) * PITCH + (e0 & 63)]) = pre0;
            *reinterpret_cast<float4*>(&cbuf[cur ^ 1][(e1 >> 6) * PITCH + (e1 & 63)]) = pre1;
            xsm[cur ^ 1][xrow * 64 + xcol] = xpre;
        }
        if (kk + 2 < 32) {
            int k2n = k2base + kk + 2;
            const float4* src = reinterpret_cast<const float4*>(g_cosT + k2n * 4096);
            pre0 = src[t];
            pre1 = src[t + 512];
            xpre = g_x[((k1base + xrow) * NH + k2n) * MD + xcol];
        }

        // compute from current buffer
        const ulonglong2* c2r = reinterpret_cast<const ulonglong2*>(&cbuf[cur][i * PITCH]);
        const ulonglong2* xr  = reinterpret_cast<const ulonglong2*>(&xsm[cur][k1sub * 64]);

        unsigned long long a0 = 0ULL, a1 = 0ULL;
#pragma unroll
        for (int qq = 0; qq < 16; qq++) {
            ulonglong2 c  = c2r[qq];   // conflict-free (pitch 68)
            ulonglong2 xv = xr[qq];    // broadcast
            a0 = fma2(mul2(C1p[2 * qq],     c.x), xv.x, a0);
            a1 = fma2(mul2(C1p[2 * qq + 1], c.y), xv.y, a1);
        }

        int k2 = k2base + kk;
        float2 f0 = upk(a0), f1 = upk(a1);
        out[(k1 * NH + k2) * MD + i] = (f0.x + f0.y) + (f1.x + f1.y);

        __syncthreads();   // iter kk readers + writers of buf[cur^1] all done
    }
}

// ---------------------------------------------------------------------------
// Launch: inputs in metadata order: grid [193,193,64], M_weight [64,64], P [64,64]
// ---------------------------------------------------------------------------
extern "C" void kernel_launch(void* const* d_in, const int* in_sizes, int n_in,
                              void* d_out, int out_size) {
    const float* grid = (const float*)d_in[0];
    const float* Mw   = (const float*)d_in[1];
    const float* P    = (const float*)d_in[2];
    float* out        = (float*)d_out;

    fused_prep<<<3072 + 1152, 256>>>(grid, Mw);
    main_kernel<<<dim3(6, NH / 8), 512>>>(P, out);
}

// round 9
// speedup vs baseline: 1.1770x; 1.1770x over previous
#include <cuda_runtime.h>

#define NH 192            // nH = nW = 193 - 2 + 1
#define HG 193            // grid H/W
#define MD 64             // vec dim m

// Scratch (allocation-free rule: __device__ globals)
__device__ float g_cosT[NH * MD * MD];   // cos(2*pi*k / T[i,j]),  3 MB
__device__ float g_x[NH * NH * MD];      // x = win_avg(grid) @ M^T, 9.4 MB

// ---- packed f32x2 helpers -------------------------------------------------
__device__ __forceinline__ unsigned long long pk(float x, float y) {
    unsigned long long r;
    asm("mov.b64 %0, {%1, %2};" : "=l"(r) : "f"(x), "f"(y));
    return r;
}
__device__ __forceinline__ float2 upk(unsigned long long v) {
    float2 t;
    asm("mov.b64 {%0, %1}, %2;" : "=f"(t.x), "=f"(t.y) : "l"(v));
    return t;
}
__device__ __forceinline__ unsigned long long fma2(unsigned long long a,
                                                   unsigned long long b,
                                                   unsigned long long c) {
    unsigned long long r;
    asm("fma.rn.f32x2 %0, %1, %2, %3;" : "=l"(r) : "l"(a), "l"(b), "l"(c));
    return r;
}

// ---- cp.async helpers -------------------------------------------------------
__device__ __forceinline__ void cp_async16(unsigned dst_smem, const void* src) {
    asm volatile("cp.async.cg.shared.global [%0], [%1], 16;"
                 :: "r"(dst_smem), "l"(src) : "memory");
}
__device__ __forceinline__ void cp_commit() {
    asm volatile("cp.async.commit_group;" ::: "memory");
}
template <int N>
__device__ __forceinline__ void cp_wait() {
    asm volatile("cp.async.wait_group %0;" :: "n"(N) : "memory");
}

// ---------------------------------------------------------------------------
// Kernel 1: cos table (float4 per thread).
// cosT[k,i,j] = cosf(2*pi*k / (i*64 + j + 2))
// ---------------------------------------------------------------------------
__global__ void __launch_bounds__(512) build_cos_table() {
    int f4 = blockIdx.x * 512 + threadIdx.x;     // 0..196607
    int e  = f4 * 4;
    int k  = e >> 12;
    int r  = e & 4095;
    int i  = r >> 6;
    int jb = r & 63;                              // multiple of 4
    const float TWO_PI = 6.2831853071795864769f;
    float fk = (float)k;
    float4 v;
    v.x = cosf(TWO_PI * fk / (float)(i * MD + jb + 2));
    v.y = cosf(TWO_PI * fk / (float)(i * MD + jb + 3));
    v.z = cosf(TWO_PI * fk / (float)(i * MD + jb + 4));
    v.w = cosf(TWO_PI * fk / (float)(i * MD + jb + 5));
    reinterpret_cast<float4*>(g_cosT)[f4] = v;
}

// ---------------------------------------------------------------------------
// Kernel 2: x[b, j] = sum_l wavg[b, l] * M[j, l]  (R8 x-body, standalone)
// ---------------------------------------------------------------------------
__global__ void __launch_bounds__(256) x_prep(const float* __restrict__ grid,
                                              const float* __restrict__ Mw) {
    __shared__ __align__(16) float sbuf[66 * 64];

    int t  = threadIdx.x;
    int q  = t >> 6;                  // 0..3 (warp-uniform)
    int jl = t & 63;

    int bid    = blockIdx.x;          // 0..1151
    int k1     = bid / 6;
    int k2base = (bid % 6) * 32;

    // stage M with pitch 66, pack row jl into f32x2 regs
    for (int e = t; e < 4096; e += 256) sbuf[(e >> 6) * 66 + (e & 63)] = Mw[e];
    __syncthreads();
    unsigned long long Mp[32];
#pragma unroll
    for (int l = 0; l < 32; l++)
        Mp[l] = pk(sbuf[jl * 66 + 2 * l], sbuf[jl * 66 + 2 * l + 1]);
    __syncthreads();

    // stage all 32 wavg rows
#pragma unroll
    for (int r = 0; r < 8; r++) {
        int e   = t + 256 * r;
        int row = e >> 6;
        int col = e & 63;
        const float* g00 = grid + ((k1 * HG + k2base + row) * MD) + col;
        sbuf[row * 64 + col] = 0.25f * (g00[0] + g00[MD] +
                                        g00[HG * MD] + g00[HG * MD + MD]);
    }
    __syncthreads();

#pragma unroll
    for (int r = 0; r < 8; r++) {
        int k2r = q + 4 * r;
        const ulonglong2* w2 = reinterpret_cast<const ulonglong2*>(&sbuf[k2r * 64]);
        unsigned long long a0 = 0ULL, a1 = 0ULL;
#pragma unroll
        for (int l = 0; l < 16; l++) {
            ulonglong2 w = w2[l];     // warp-uniform row -> broadcast
            a0 = fma2(Mp[2 * l],     w.x, a0);
            a1 = fma2(Mp[2 * l + 1], w.y, a1);
        }
        float2 f0 = upk(a0), f1 = upk(a1);
        g_x[(k1 * NH + k2base + k2r) * MD + jl] = (f0.x + f0.y) + (f1.x + f1.y);
    }
}

// ---------------------------------------------------------------------------
// Main kernel: Nk[b,i] = sum_j x[b,j] * P[i,j] * cos1[k1,i,j] * cos2[k2,i,j]
//
// Chebyshev recurrence: d_k = P*cos1*cos(k*theta) with
//   d_{k+1} = 2cos(theta)*d_k - d_{k-1}
// held entirely in f32x2 registers -> NO cos smem traffic, no per-iter barrier.
// 512 threads: t = (k1sub<<7) | (i<<1) | jh; jh splits j into 32+32.
// CTA covers 4 k1 x 64 k2; grid (3 k2chunks, 48 k1tiles) = 144 CTAs = 1 wave.
// x staged in 16-k2 blocks via cp.async (double-buffered, 2 barriers / 16 iters).
// jh halves combined with one shfl_xor; even lanes store.
// ---------------------------------------------------------------------------
__global__ void __launch_bounds__(512, 1) main_kernel(const float* __restrict__ P,
                                                      float* __restrict__ out) {
    __shared__ __align__(16) float xs[2][16][4][64];   // 32 KB

    const unsigned long long SGN = 0x8000000080000000ULL;

    int t     = threadIdx.x;
    int jh    = t & 1;
    int i     = (t >> 1) & 63;
    int k1sub = t >> 7;                 // 0..3
    int k1base = blockIdx.y * 4;
    int k1     = k1base + k1sub;
    int k2s    = blockIdx.x * 64;

    // ---- init: tc = 2*cos(theta) (slice k=1); d state at k2s, k2s-1 ----
    unsigned long long tc[16], dcur[16], ndprev[16];
    {
        int ro = (i * MD + jh * 32) >> 2;                 // float4 row offset
        const float4* c1r = reinterpret_cast<const float4*>(g_cosT) + (k1 << 10) + ro;
        const float4* t1r = reinterpret_cast<const float4*>(g_cosT) + (1 << 10) + ro;
        const float4* c2a = reinterpret_cast<const float4*>(g_cosT) + (k2s << 10) + ro;
        int k2m = (k2s == 0) ? 1 : (k2s - 1);
        const float4* c2b = reinterpret_cast<const float4*>(g_cosT) + (k2m << 10) + ro;
        const float4* pr  = reinterpret_cast<const float4*>(P) + ((i * MD + jh * 32) >> 2);
#pragma unroll
        for (int p = 0; p < 8; p++) {
            float4 c1 = c1r[p];
            float4 pp = pr[p];
            float4 th = t1r[p];
            float4 ca = c2a[p];
            float4 cb = c2b[p];
            float e0 = pp.x * c1.x, e1 = pp.y * c1.y;   // C1 = P*cos1
            float e2 = pp.z * c1.z, e3 = pp.w * c1.w;
            tc[2 * p]     = pk(2.f * th.x, 2.f * th.y);
            tc[2 * p + 1] = pk(2.f * th.z, 2.f * th.w);
            dcur[2 * p]     = pk(e0 * ca.x, e1 * ca.y);
            dcur[2 * p + 1] = pk(e2 * ca.z, e3 * ca.w);
            ndprev[2 * p]     = pk(-e0 * cb.x, -e1 * cb.y);
            ndprev[2 * p + 1] = pk(-e2 * cb.z, -e3 * cb.w);
        }
    }

    // ---- cp.async x staging: thread copies float4 f = t and t+512 of each block ----
    int s_  = t >> 7;                                   // reuse: f=t -> s=t>>8? compute per f below
    (void)s_;
    unsigned xs_base = (unsigned)__cvta_generic_to_shared(&xs[0][0][0][0]);

    auto issue_block = [&](int b) {
        int kb = k2s + b * 16;
        unsigned dbase = xs_base + ((b & 1) ? 16384u : 0u);
#pragma unroll
        for (int h = 0; h < 2; h++) {
            int f  = t + 512 * h;                       // 0..1023
            int s  = f >> 8;                            // k1 row 0..3
            int rm = f & 255;
            int r  = rm >> 4;                           // k2 offset 0..15
            int j4 = rm & 15;
            const float4* src = reinterpret_cast<const float4*>(g_x) +
                                (((k1base + s) * NH + kb + r) << 4) + j4;
            unsigned dst = dbase + (((r * 4 + s) * 64 + j4 * 4) << 2);
            cp_async16(dst, src);
        }
        cp_commit();
    };

    issue_block(0);
    if (64 > 16) issue_block(1);

    // ---- main loop: 4 blocks x 16 k2 ----
    for (int b = 0; b < 4; b++) {
        if (b >= 1) {
            __syncthreads();            // readers of buf[(b+1)&1] (block b-1) done
            if (b + 1 < 4) issue_block(b + 1);
        }
        if (b + 1 < 4) cp_wait<1>(); else cp_wait<0>();
        __syncthreads();                // block b visible to all

        const float* xbase = &xs[b & 1][0][k1sub][jh * 32];

#pragma unroll 2
        for (int r = 0; r < 16; r++) {
            const ulonglong2* xr =
                reinterpret_cast<const ulonglong2*>(xbase + r * 256);
            unsigned long long a0 = 0ULL, a1 = 0ULL;
#pragma unroll
            for (int p = 0; p < 8; p++) {
                ulonglong2 xv = xr[p];                  // broadcast-ish LDS.128
                a0 = fma2(dcur[2 * p],     xv.x, a0);
                a1 = fma2(dcur[2 * p + 1], xv.y, a1);
            }
            // Chebyshev step: d_{k+1} = tc*d_k - d_{k-1}; neg via ALU-pipe XOR
#pragma unroll
            for (int p = 0; p < 16; p++) {
                unsigned long long dn = fma2(tc[p], dcur[p], ndprev[p]);
                ndprev[p] = dcur[p] ^ SGN;
                dcur[p]   = dn;
            }
            float2 f0 = upk(a0), f1 = upk(a1);
            float part = (f0.x + f0.y) + (f1.x + f1.y);
            float full = part + __shfl_xor_sync(0xFFFFFFFFu, part, 1);
            if (jh == 0) {
                int k2 = k2s + b * 16 + r;
                out[(k1 * NH + k2) * MD + i] = full;
            }
        }
    }
}

// ---------------------------------------------------------------------------
// Launch: inputs in metadata order: grid [193,193,64], M_weight [64,64], P [64,64]
// ---------------------------------------------------------------------------
extern "C" void kernel_launch(void* const* d_in, const int* in_sizes, int n_in,
                              void* d_out, int out_size) {
    const float* grid = (const float*)d_in[0];
    const float* Mw   = (const float*)d_in[1];
    const float* P    = (const float*)d_in[2];
    float* out        = (float*)d_out;

    build_cos_table<<<384, 512>>>();
    x_prep<<<1152, 256>>>(grid, Mw);
    main_kernel<<<dim3(3, 48), 512>>>(P, out);
}